// round 8
// baseline (speedup 1.0000x reference)
#include <cuda_runtime.h>
#include <cuda_bf16.h>
#include <cstdint>
#include <math.h>

// ---------------------------------------------------------------------------
// SiglipAttention: B=8, N=1024, D=1152, H=16, Hd=72
// Outputs (concatenated in d_out): out [B,N,D] fp32, attn_probs [B,H,N,N] fp32
// ---------------------------------------------------------------------------

#define BD   8
#define SEQ  1024
#define DIM  1152
#define NH   16
#define HD   72
#define MTOT (BD * SEQ)                 // 8192
#define QKV_ELEMS (BD * NH * SEQ * HD)  // 9437184
#define OUT_ELEMS (BD * SEQ * DIM)      // 9437184
#define WELEMS (DIM * DIM)              // 1327104
#define SCALE_F 0.117851130197757931f   // 72^-0.5

// Scratch (allocation-free rule: __device__ globals).  Everything the MMA
// mainloops touch is PRE-SPLIT into hi/lo bf16 exactly once.
__device__ __nv_bfloat16 g_xh[OUT_ELEMS],  g_xl[OUT_ELEMS];    // x  [B*N, DIM]
__device__ __nv_bfloat16 g_wh[4][WELEMS],  g_wl[4][WELEMS];    // q,k,v,o weights
__device__ __nv_bfloat16 g_qh[QKV_ELEMS],  g_ql[QKV_ELEMS];    // Q [B,H,N,Hd]
__device__ __nv_bfloat16 g_kh[QKV_ELEMS],  g_kl[QKV_ELEMS];    // K [B,H,N,Hd]
__device__ __nv_bfloat16 g_vh[QKV_ELEMS],  g_vl[QKV_ELEMS];    // V [B,H,N,Hd]
__device__ __nv_bfloat16 g_ch[OUT_ELEMS],  g_cl[OUT_ELEMS];    // ctx [B,N,D]

// ===========================================================================
// HMMA helpers (sm_80+ mma.sync path — tcgen05 unavailable: harness PTX
// targets sm_103 base, not sm_103a)
// ===========================================================================
__device__ __forceinline__ uint32_t smem_u32(const void* p) {
    uint32_t a;
    asm("{ .reg .u64 t; cvta.to.shared.u64 t, %1; cvt.u32.u64 %0, t; }"
        : "=r"(a) : "l"(p));
    return a;
}

__device__ __forceinline__ void ldsm_x4(uint32_t& r0, uint32_t& r1,
                                        uint32_t& r2, uint32_t& r3, uint32_t a) {
    asm volatile("ldmatrix.sync.aligned.m8n8.x4.shared.b16 {%0,%1,%2,%3}, [%4];"
                 : "=r"(r0), "=r"(r1), "=r"(r2), "=r"(r3) : "r"(a));
}
__device__ __forceinline__ void ldsm_x2(uint32_t& r0, uint32_t& r1, uint32_t a) {
    asm volatile("ldmatrix.sync.aligned.m8n8.x2.shared.b16 {%0,%1}, [%2];"
                 : "=r"(r0), "=r"(r1) : "r"(a));
}
__device__ __forceinline__ void mma16816(float* c,
                                         uint32_t a0, uint32_t a1, uint32_t a2, uint32_t a3,
                                         uint32_t b0, uint32_t b1) {
    asm volatile(
        "mma.sync.aligned.m16n8k16.row.col.f32.bf16.bf16.f32 "
        "{%0,%1,%2,%3}, {%4,%5,%6,%7}, {%8,%9}, {%0,%1,%2,%3};"
        : "+f"(c[0]), "+f"(c[1]), "+f"(c[2]), "+f"(c[3])
        : "r"(a0), "r"(a1), "r"(a2), "r"(a3), "r"(b0), "r"(b1));
}

// split fp32x4 -> hi bf16x4 + lo bf16x4 (packed as uint2 each)
__device__ __forceinline__ void split8(uint2& hi, uint2& lo, float4 v) {
    __nv_bfloat162 h01 = __floats2bfloat162_rn(v.x, v.y);
    __nv_bfloat162 h23 = __floats2bfloat162_rn(v.z, v.w);
    float rx = v.x - __bfloat162float(h01.x);
    float ry = v.y - __bfloat162float(h01.y);
    float rz = v.z - __bfloat162float(h23.x);
    float rw = v.w - __bfloat162float(h23.y);
    hi = make_uint2(*(uint32_t*)&h01, *(uint32_t*)&h23);
    __nv_bfloat162 l01 = __floats2bfloat162_rn(rx, ry);
    __nv_bfloat162 l23 = __floats2bfloat162_rn(rz, rw);
    lo = make_uint2(*(uint32_t*)&l01, *(uint32_t*)&l23);
}

// split fp32x2 -> packed bf16x2 hi + bf16x2 lo
__device__ __forceinline__ void split2(uint32_t& hi, uint32_t& lo, float x, float y) {
    __nv_bfloat162 h = __floats2bfloat162_rn(x, y);
    float rx = x - __bfloat162float(h.x);
    float ry = y - __bfloat162float(h.y);
    hi = *(uint32_t*)&h;
    __nv_bfloat162 l = __floats2bfloat162_rn(rx, ry);
    lo = *(uint32_t*)&l;
}

// ===========================================================================
// Kernel 0: pre-split x and the 4 weight matrices to hi/lo bf16 (once).
// Each thread handles one float4 (4 elements).
// ===========================================================================
#define X_F4   (OUT_ELEMS / 4)   // 2359296
#define W_F4   (WELEMS / 4)      // 331776
#define PREP_TOTAL (X_F4 + 4 * W_F4)

__global__ __launch_bounds__(256) void prep_kernel(
    const float* __restrict__ x,
    const float* __restrict__ qw, const float* __restrict__ kw,
    const float* __restrict__ vw, const float* __restrict__ ow)
{
    const size_t i = (size_t)blockIdx.x * 256 + threadIdx.x;
    if (i >= PREP_TOTAL) return;
    const float* src;
    __nv_bfloat16 *dh, *dl;
    size_t e;
    if (i < X_F4) {
        src = x; dh = g_xh; dl = g_xl; e = i;
    } else {
        const size_t wi = i - X_F4;
        const int    wsel = (int)(wi / W_F4);
        e = wi % W_F4;
        src = (wsel == 0) ? qw : (wsel == 1) ? kw : (wsel == 2) ? vw : ow;
        dh = g_wh[wsel]; dl = g_wl[wsel];
    }
    float4 v = *(const float4*)(src + e * 4);
    uint2 h, l;
    split8(h, l, v);
    *(uint2*)(dh + e * 4) = h;
    *(uint2*)(dl + e * 4) = l;
}

// ===========================================================================
// Common bf16x3 HMMA GEMM core on PRE-SPLIT inputs:
//   y[128,128]tile = A[M,K] @ W[N,K]^T ;  staging is pure uint4 copies.
// MODE 0: head-scatter epilogue -> hi/lo bf16 (qkv)
// MODE 1: plain fp32 [M,DIM] epilogue (o-proj)
// ===========================================================================
#define TSTR 40   // bf16 elements per smem row (80 bytes, conflict-free)

template <int MODE>
__device__ __forceinline__ void tc_gemm_tile(
    const __nv_bfloat16* __restrict__ Agh, const __nv_bfloat16* __restrict__ Agl,
    const __nv_bfloat16* __restrict__ Wgh, const __nv_bfloat16* __restrict__ Wgl,
    const float* __restrict__ bias,
    float* __restrict__ dst, __nv_bfloat16* __restrict__ dsth,
    __nv_bfloat16* __restrict__ dstl,
    int m0, int n0)
{
    __shared__ __nv_bfloat16 sAh[128 * TSTR], sAl[128 * TSTR];
    __shared__ __nv_bfloat16 sBh[128 * TSTR], sBl[128 * TSTR];

    const int tid  = threadIdx.x;
    const int lane = tid & 31;
    const int wid  = tid >> 5;
    const int wm   = (wid >> 2) * 64;   // warp m-offset (0/64)
    const int wn   = (wid & 3) * 32;    // warp n-offset (0/32/64/96)

    const uint32_t ah = smem_u32(sAh), al = smem_u32(sAl);
    const uint32_t bh = smem_u32(sBh), bl = smem_u32(sBl);

    float acc[4][4][4];
#pragma unroll
    for (int i = 0; i < 4; i++)
#pragma unroll
        for (int j = 0; j < 4; j++)
#pragma unroll
            for (int q = 0; q < 4; q++) acc[i][j][q] = 0.f;

    const uint32_t a_off = (wm + (lane & 15)) * (TSTR * 2) + (lane >> 4) * 16;
    const uint32_t b_row_base = wn + (lane & 7);
    const uint32_t b_off = ((lane >> 3) & 1) * 16;

    for (int k0 = 0; k0 < DIM; k0 += 32) {
        __syncthreads();
        // stage: 128 rows x 32 bf16 per array = 4 uint4/row; 512 uint4/array
#pragma unroll
        for (int t = 0; t < 2; t++) {
            const int idx = tid + t * 256;        // 0..511
            const int row = idx >> 2;
            const int c8  = (idx & 3) * 8;
            const size_t ga = (size_t)(m0 + row) * DIM + k0 + c8;
            const size_t gb = (size_t)(n0 + row) * DIM + k0 + c8;
            *(uint4*)(sAh + row * TSTR + c8) = *(const uint4*)(Agh + ga);
            *(uint4*)(sAl + row * TSTR + c8) = *(const uint4*)(Agl + ga);
            *(uint4*)(sBh + row * TSTR + c8) = *(const uint4*)(Wgh + gb);
            *(uint4*)(sBl + row * TSTR + c8) = *(const uint4*)(Wgl + gb);
        }
        __syncthreads();

#pragma unroll
        for (int ks = 0; ks < 2; ks++) {
            uint32_t Ah[4][4], Al[4][4], Bh[4][2], Bl[4][2];
#pragma unroll
            for (int mf = 0; mf < 4; mf++) {
                const uint32_t addr = a_off + mf * 16 * (TSTR * 2) + ks * 32;
                ldsm_x4(Ah[mf][0], Ah[mf][1], Ah[mf][2], Ah[mf][3], ah + addr);
                ldsm_x4(Al[mf][0], Al[mf][1], Al[mf][2], Al[mf][3], al + addr);
            }
#pragma unroll
            for (int nf = 0; nf < 4; nf++) {
                const uint32_t addr = (b_row_base + nf * 8) * (TSTR * 2) + ks * 32 + b_off;
                ldsm_x2(Bh[nf][0], Bh[nf][1], bh + addr);
                ldsm_x2(Bl[nf][0], Bl[nf][1], bl + addr);
            }
#pragma unroll
            for (int mf = 0; mf < 4; mf++)
#pragma unroll
                for (int nf = 0; nf < 4; nf++) {
                    mma16816(acc[mf][nf], Ah[mf][0], Ah[mf][1], Ah[mf][2], Ah[mf][3],
                             Bh[nf][0], Bh[nf][1]);
                    mma16816(acc[mf][nf], Al[mf][0], Al[mf][1], Al[mf][2], Al[mf][3],
                             Bh[nf][0], Bh[nf][1]);
                    mma16816(acc[mf][nf], Ah[mf][0], Ah[mf][1], Ah[mf][2], Ah[mf][3],
                             Bl[nf][0], Bl[nf][1]);
                }
        }
    }

    const int r_base = m0 + wm + (lane >> 2);
    const int c_base = n0 + wn + (lane & 3) * 2;
#pragma unroll
    for (int mf = 0; mf < 4; mf++) {
#pragma unroll
        for (int nf = 0; nf < 4; nf++) {
            const int col = c_base + nf * 8;
            const float bx = bias[col], by = bias[col + 1];
#pragma unroll
            for (int half = 0; half < 2; half++) {
                const int row = r_base + mf * 16 + half * 8;
                const float vx = acc[mf][nf][half * 2 + 0] + bx;
                const float vy = acc[mf][nf][half * 2 + 1] + by;
                if (MODE == 0) {
                    const int bb = row >> 10, n = row & 1023;
                    const int hdh = col / HD, hd = col % HD;
                    const size_t ga = ((size_t)(bb * NH + hdh) * SEQ + n) * HD + hd;
                    uint32_t hi, lo;
                    split2(hi, lo, vx, vy);
                    *(uint32_t*)(dsth + ga) = hi;
                    *(uint32_t*)(dstl + ga) = lo;
                } else {
                    float2 v; v.x = vx; v.y = vy;
                    *(float2*)(dst + (size_t)row * DIM + col) = v;
                }
            }
        }
    }
}

// Kernel 1: QKV projection -> pre-split bf16 head layout
__global__ __launch_bounds__(256) void qkv_tc_kernel(
    const float* __restrict__ qb, const float* __restrict__ kb,
    const float* __restrict__ vb)
{
    const int proj = blockIdx.z;
    const float* bias = (proj == 0) ? qb : (proj == 1) ? kb : vb;
    __nv_bfloat16* dh = (proj == 0) ? g_qh : (proj == 1) ? g_kh : g_vh;
    __nv_bfloat16* dl = (proj == 0) ? g_ql : (proj == 1) ? g_kl : g_vl;
    tc_gemm_tile<0>(g_xh, g_xl, g_wh[proj], g_wl[proj], bias,
                    nullptr, dh, dl, blockIdx.y * 128, blockIdx.x * 128);
}

// Kernel 5: O projection (ctx pre-split by pv) -> fp32 out
__global__ __launch_bounds__(256) void oproj_tc_kernel(
    const float* __restrict__ ob, float* __restrict__ out)
{
    tc_gemm_tile<1>(g_ch, g_cl, g_wh[3], g_wl[3], ob,
                    out, nullptr, nullptr, blockIdx.y * 128, blockIdx.x * 128);
}

// ===========================================================================
// Kernel 2: FUSED scores + softmax.  16 q-rows x 1024 keys per CTA.
// Q frags + K tiles load pre-split bf16 (pure copies).
// ===========================================================================
#define FS_KSTR 88
#define FS_SSTR 1026
#define FS_S_BYTES (16 * FS_SSTR * 4)            // 65664
#define FS_K_BYTES (128 * FS_KSTR * 2)           // 22528 per tile
#define FS_SMEM (FS_S_BYTES + 2 * FS_K_BYTES)    // 110720

__global__ __launch_bounds__(256, 2) void fused_scores_softmax_kernel(
    float* __restrict__ probs)
{
    extern __shared__ char fsm[];
    float* S = (float*)fsm;
    __nv_bfloat16* Kh = (__nv_bfloat16*)(fsm + FS_S_BYTES);
    __nv_bfloat16* Kl = Kh + 128 * FS_KSTR;

    const int tid  = threadIdx.x;
    const int lane = tid & 31;
    const int w    = tid >> 5;
    const int q0   = blockIdx.x * 16;
    const int bhx  = blockIdx.y;

    const __nv_bfloat16* Qgh = g_qh + (size_t)bhx * SEQ * HD + (size_t)q0 * HD;
    const __nv_bfloat16* Qgl = g_ql + (size_t)bhx * SEQ * HD + (size_t)q0 * HD;
    const __nv_bfloat16* Kgh = g_kh + (size_t)bhx * SEQ * HD;
    const __nv_bfloat16* Kgl = g_kl + (size_t)bhx * SEQ * HD;

    // ---- load Q A-fragments directly (pre-split bf16, pure loads) ----
    uint32_t Qh[5][4], Ql[5][4];
    {
        const int r  = lane >> 2;
        const int c0 = (lane & 3) * 2;
#pragma unroll
        for (int ks = 0; ks < 5; ks++)
#pragma unroll
            for (int j = 0; j < 4; j++) {
                const int rr = r + (j & 1) * 8;
                const int cc = ks * 16 + c0 + (j >> 1) * 8;
                uint32_t h = 0, l = 0;
                if (cc < 72) {
                    h = *(const uint32_t*)(Qgh + (size_t)rr * HD + cc);
                    l = *(const uint32_t*)(Qgl + (size_t)rr * HD + cc);
                }
                Qh[ks][j] = h; Ql[ks][j] = l;
            }
    }

    // zero K pad columns [72,80) once
    for (int r = tid; r < 128; r += 256) {
        *(uint2*)(Kh + r * FS_KSTR + 72) = make_uint2(0, 0);
        *(uint2*)(Kh + r * FS_KSTR + 76) = make_uint2(0, 0);
        *(uint2*)(Kl + r * FS_KSTR + 72) = make_uint2(0, 0);
        *(uint2*)(Kl + r * FS_KSTR + 76) = make_uint2(0, 0);
    }

    const uint32_t kh = smem_u32(Kh), kl = smem_u32(Kl);
    const uint32_t b_row = w * 16 + (lane & 7);
    const uint32_t b_off = ((lane >> 3) & 1) * 16;

    for (int kb = 0; kb < 8; kb++) {
        __syncthreads();
        // stage K tile: pure uint4 copies (72 bf16 = 9 uint4 per row)
        for (int idx = tid; idx < 128 * 9; idx += 256) {
            const int row = idx / 9;
            const int c8  = (idx % 9) * 8;
            const size_t ga = (size_t)(kb * 128 + row) * HD + c8;
            *(uint4*)(Kh + row * FS_KSTR + c8) = *(const uint4*)(Kgh + ga);
            *(uint4*)(Kl + row * FS_KSTR + c8) = *(const uint4*)(Kgl + ga);
        }
        __syncthreads();

        float acc[2][4];
#pragma unroll
        for (int nf = 0; nf < 2; nf++)
#pragma unroll
            for (int q = 0; q < 4; q++) acc[nf][q] = 0.f;

#pragma unroll
        for (int ks = 0; ks < 5; ks++) {
            uint32_t Bh[2][2], Bl[2][2];
#pragma unroll
            for (int nf = 0; nf < 2; nf++) {
                const uint32_t addr = (b_row + nf * 8) * (FS_KSTR * 2) + ks * 32 + b_off;
                ldsm_x2(Bh[nf][0], Bh[nf][1], kh + addr);
                ldsm_x2(Bl[nf][0], Bl[nf][1], kl + addr);
            }
#pragma unroll
            for (int nf = 0; nf < 2; nf++) {
                mma16816(acc[nf], Qh[ks][0], Qh[ks][1], Qh[ks][2], Qh[ks][3],
                         Bh[nf][0], Bh[nf][1]);
                mma16816(acc[nf], Ql[ks][0], Ql[ks][1], Ql[ks][2], Ql[ks][3],
                         Bh[nf][0], Bh[nf][1]);
                mma16816(acc[nf], Qh[ks][0], Qh[ks][1], Qh[ks][2], Qh[ks][3],
                         Bl[nf][0], Bl[nf][1]);
            }
        }

        const int r = lane >> 2;
        const int c = (lane & 3) * 2;
#pragma unroll
        for (int nf = 0; nf < 2; nf++)
#pragma unroll
            for (int half = 0; half < 2; half++) {
                const int row = r + half * 8;
                const int col = kb * 128 + w * 16 + nf * 8 + c;
                float2 v;
                v.x = acc[nf][half * 2 + 0] * SCALE_F;
                v.y = acc[nf][half * 2 + 1] * SCALE_F;
                *(float2*)(S + row * FS_SSTR + col) = v;
            }
    }
    __syncthreads();

    // ---- softmax: warp w handles rows 2w, 2w+1 ----
#pragma unroll
    for (int rr = 0; rr < 2; rr++) {
        const int row = w * 2 + rr;
        float2 v[16];
#pragma unroll
        for (int i = 0; i < 16; i++)
            v[i] = *(const float2*)(S + row * FS_SSTR + lane * 2 + i * 64);
        float m = -1e30f;
#pragma unroll
        for (int i = 0; i < 16; i++) m = fmaxf(m, fmaxf(v[i].x, v[i].y));
#pragma unroll
        for (int o = 16; o; o >>= 1) m = fmaxf(m, __shfl_xor_sync(~0u, m, o));
        float s = 0.f;
#pragma unroll
        for (int i = 0; i < 16; i++) {
            v[i].x = __expf(v[i].x - m);
            v[i].y = __expf(v[i].y - m);
            s += v[i].x + v[i].y;
        }
#pragma unroll
        for (int o = 16; o; o >>= 1) s += __shfl_xor_sync(~0u, s, o);
        const float inv = 1.f / s;
        float* pg = probs + ((size_t)bhx * SEQ + q0 + row) * SEQ;
#pragma unroll
        for (int i = 0; i < 16; i++) {
            float2 o2;
            o2.x = v[i].x * inv;
            o2.y = v[i].y * inv;
            *(float2*)(pg + lane * 2 + i * 64) = o2;
        }
    }
}

// ===========================================================================
// Kernel 4: PV GEMM.  ctx = P @ V -> pre-split bf16 [B,N,D].
// P split once from fp32 probs; V loads pre-split bf16 (transposed store).
// ===========================================================================
#define PV_TS 72
#define PV_P_TILE (128 * PV_TS)
#define PV_V_TILE (96 * PV_TS)
#define PV_SMEM_BYTES ((2 * PV_P_TILE + 2 * PV_V_TILE) * 2)   // 64512

__global__ __launch_bounds__(256) void pv_tc_kernel(const float* __restrict__ probs)
{
    extern __shared__ __nv_bfloat16 pv_sm[];
    __nv_bfloat16* sPh = pv_sm;
    __nv_bfloat16* sPl = pv_sm + PV_P_TILE;
    __nv_bfloat16* sVh = pv_sm + 2 * PV_P_TILE;
    __nv_bfloat16* sVl = pv_sm + 2 * PV_P_TILE + PV_V_TILE;

    const int tid  = threadIdx.x;
    const int lane = tid & 31;
    const int wid  = tid >> 5;
    const int wm   = (wid >> 2) * 64;   // 0/64
    const int wn   = (wid & 3) * 24;    // 0/24/48/72
    const int m0 = blockIdx.x * 128;
    const int bhx = blockIdx.y;
    const int bb = bhx >> 4, hh = bhx & 15;

    const float* Pg = probs + (size_t)bhx * SEQ * SEQ;
    const __nv_bfloat16* Vgh = g_vh + (size_t)bhx * SEQ * HD;
    const __nv_bfloat16* Vgl = g_vl + (size_t)bhx * SEQ * HD;

    // zero V pad rows [72,96)
    for (int i = tid; i < 24 * 18; i += 256) {
        const int r = 72 + i / 18;
        const int c = (i % 18) * 4;
        *(uint2*)(sVh + r * PV_TS + c) = make_uint2(0, 0);
        *(uint2*)(sVl + r * PV_TS + c) = make_uint2(0, 0);
    }

    const uint32_t ah = smem_u32(sPh), al = smem_u32(sPl);
    const uint32_t bh = smem_u32(sVh), bl = smem_u32(sVl);

    float acc[4][3][4];
#pragma unroll
    for (int i = 0; i < 4; i++)
#pragma unroll
        for (int j = 0; j < 3; j++)
#pragma unroll
            for (int q = 0; q < 4; q++) acc[i][j][q] = 0.f;

    const uint32_t a_off = (wm + (lane & 15)) * (PV_TS * 2) + (lane >> 4) * 16;
    const uint32_t b_row_base = wn + (lane & 7);
    const uint32_t b_off = ((lane >> 3) & 1) * 16;

    for (int k0 = 0; k0 < SEQ; k0 += 64) {
        __syncthreads();
        // stage P tile 128x64 fp32 -> hi/lo (split once per element)
#pragma unroll
        for (int t = 0; t < 8; t++) {
            const int idx = tid + t * 256;
            const int row = idx >> 4;
            const int c4  = (idx & 15) << 2;
            float4 pvv = *(const float4*)(Pg + (size_t)(m0 + row) * SEQ + k0 + c4);
            uint2 h, l;
            split8(h, l, pvv);
            *(uint2*)(sPh + row * PV_TS + c4) = h;
            *(uint2*)(sPl + row * PV_TS + c4) = l;
        }
        // stage V 64x72 pre-split bf16, transposed -> [n][k]
        for (int idx = tid; idx < 64 * 36; idx += 256) {
            const int srow = idx / 36;
            const int c2   = (idx % 36) * 2;
            const uint32_t h = *(const uint32_t*)(Vgh + (size_t)(k0 + srow) * HD + c2);
            const uint32_t l = *(const uint32_t*)(Vgl + (size_t)(k0 + srow) * HD + c2);
            sVh[(c2 + 0) * PV_TS + srow] = ((const __nv_bfloat16*)&h)[0];
            sVh[(c2 + 1) * PV_TS + srow] = ((const __nv_bfloat16*)&h)[1];
            sVl[(c2 + 0) * PV_TS + srow] = ((const __nv_bfloat16*)&l)[0];
            sVl[(c2 + 1) * PV_TS + srow] = ((const __nv_bfloat16*)&l)[1];
        }
        __syncthreads();

#pragma unroll
        for (int ks = 0; ks < 4; ks++) {
            uint32_t Ah[4][4], Al[4][4], Bh[3][2], Bl[3][2];
#pragma unroll
            for (int mf = 0; mf < 4; mf++) {
                const uint32_t addr = a_off + mf * 16 * (PV_TS * 2) + ks * 32;
                ldsm_x4(Ah[mf][0], Ah[mf][1], Ah[mf][2], Ah[mf][3], ah + addr);
                ldsm_x4(Al[mf][0], Al[mf][1], Al[mf][2], Al[mf][3], al + addr);
            }
#pragma unroll
            for (int nf = 0; nf < 3; nf++) {
                const uint32_t addr = (b_row_base + nf * 8) * (PV_TS * 2) + ks * 32 + b_off;
                ldsm_x2(Bh[nf][0], Bh[nf][1], bh + addr);
                ldsm_x2(Bl[nf][0], Bl[nf][1], bl + addr);
            }
#pragma unroll
            for (int mf = 0; mf < 4; mf++)
#pragma unroll
                for (int nf = 0; nf < 3; nf++) {
                    mma16816(acc[mf][nf], Ah[mf][0], Ah[mf][1], Ah[mf][2], Ah[mf][3],
                             Bh[nf][0], Bh[nf][1]);
                    mma16816(acc[mf][nf], Al[mf][0], Al[mf][1], Al[mf][2], Al[mf][3],
                             Bh[nf][0], Bh[nf][1]);
                    mma16816(acc[mf][nf], Ah[mf][0], Ah[mf][1], Ah[mf][2], Ah[mf][3],
                             Bl[nf][0], Bl[nf][1]);
                }
        }
    }

    // epilogue: split ctx to hi/lo bf16 (consumed by oproj)
    const int r_base = m0 + wm + (lane >> 2);
    const int c_base = wn + (lane & 3) * 2;
#pragma unroll
    for (int mf = 0; mf < 4; mf++)
#pragma unroll
        for (int nf = 0; nf < 3; nf++) {
            const int col = c_base + nf * 8;
            if (col < HD) {
#pragma unroll
                for (int half = 0; half < 2; half++) {
                    const int row = r_base + mf * 16 + half * 8;
                    const size_t ga = ((size_t)bb * SEQ + row) * DIM + hh * HD + col;
                    uint32_t hi, lo;
                    split2(hi, lo, acc[mf][nf][half * 2 + 0],
                           acc[mf][nf][half * 2 + 1]);
                    *(uint32_t*)(g_ch + ga) = hi;
                    *(uint32_t*)(g_cl + ga) = lo;
                }
            }
        }
}

// ---------------------------------------------------------------------------
extern "C" void kernel_launch(void* const* d_in, const int* in_sizes, int n_in,
                              void* d_out, int out_size)
{
    const float* x  = (const float*)d_in[0];
    const float* qw = (const float*)d_in[1];
    const float* qb = (const float*)d_in[2];
    const float* kw = (const float*)d_in[3];
    const float* kb = (const float*)d_in[4];
    const float* vw = (const float*)d_in[5];
    const float* vb = (const float*)d_in[6];
    const float* ow = (const float*)d_in[7];
    const float* ob = (const float*)d_in[8];

    float* out   = (float*)d_out;            // [B,N,D]
    float* probs = out + OUT_ELEMS;          // [B,H,N,N]

    cudaFuncSetAttribute(fused_scores_softmax_kernel,
                         cudaFuncAttributeMaxDynamicSharedMemorySize,
                         FS_SMEM);
    cudaFuncSetAttribute(pv_tc_kernel,
                         cudaFuncAttributeMaxDynamicSharedMemorySize,
                         PV_SMEM_BYTES);

    prep_kernel<<<(PREP_TOTAL + 255) / 256, 256>>>(x, qw, kw, vw, ow);

    dim3 gq(DIM / 128, MTOT / 128, 3);       // (9, 64, 3)
    qkv_tc_kernel<<<gq, 256>>>(qb, kb, vb);

    dim3 gs(SEQ / 16, BD * NH);              // (64, 128)
    fused_scores_softmax_kernel<<<gs, 256, FS_SMEM>>>(probs);

    dim3 gp(SEQ / 128, BD * NH);             // (8, 128)
    pv_tc_kernel<<<gp, 256, PV_SMEM_BYTES>>>(probs);

    dim3 go(DIM / 128, MTOT / 128);          // (9, 64)
    oproj_tc_kernel<<<go, 256>>>(ob, out);
}